// round 2
// baseline (speedup 1.0000x reference)
#include <cuda_runtime.h>

// SampleConditionalGMM: out = stds[b, lut[label], c] * noise + means[b, lut[label], c]
// Shapes: label_map [2,160,160,160,1] i32, means/stds [2,25,2] f32,
//         noise/out [2,160,160,160,2] f32.

#define NL 25          // number of generation labels
#define MAXL 48        // max label value + 1
#define CCH 2          // channels
#define VOX 4096000    // 160*160*160 voxels per batch
#define VPB 1024       // voxels per block (256 threads * 4 voxels)

__constant__ int c_gen_labels[NL] = {
    0, 2, 3, 4, 5, 7, 8, 10, 11, 12, 13, 14, 15, 16, 17, 18,
    24, 26, 28, 41, 42, 43, 44, 46, 47
};

__global__ __launch_bounds__(256)
void gmm_sample_kernel(const int*   __restrict__ label,
                       const float* __restrict__ means,
                       const float* __restrict__ stds,
                       const float* __restrict__ noise,
                       float*       __restrict__ out)
{
    // Shared tables indexed directly by label VALUE (not compacted index):
    // one LDS per lookup, no LUT chain.
    __shared__ float s_mean[MAXL * CCH];
    __shared__ float s_std [MAXL * CCH];

    const long long base = (long long)blockIdx.x * VPB;   // first voxel of block
    const int b = (int)(base / VOX);                      // batch (constant per block)
    const int t = threadIdx.x;

    if (t < NL * CCH) {
        const int lbl = c_gen_labels[t >> 1];
        const int ch  = t & 1;
        s_mean[lbl * CCH + ch] = means[b * NL * CCH + t];
        s_std [lbl * CCH + ch] = stds [b * NL * CCH + t];
    }
    __syncthreads();

    const long long v = base + (long long)t * 4;          // 4 voxels per thread

    const int4 lb = *reinterpret_cast<const int4*>(label + v);

    const float4* np = reinterpret_cast<const float4*>(noise + v * CCH);
    const float4 n0 = np[0];
    const float4 n1 = np[1];

    float4 o0, o1;
    {
        const int i0 = lb.x * CCH, i1 = lb.y * CCH;
        o0.x = fmaf(s_std[i0 + 0], n0.x, s_mean[i0 + 0]);
        o0.y = fmaf(s_std[i0 + 1], n0.y, s_mean[i0 + 1]);
        o0.z = fmaf(s_std[i1 + 0], n0.z, s_mean[i1 + 0]);
        o0.w = fmaf(s_std[i1 + 1], n0.w, s_mean[i1 + 1]);
    }
    {
        const int i2 = lb.z * CCH, i3 = lb.w * CCH;
        o1.x = fmaf(s_std[i2 + 0], n1.x, s_mean[i2 + 0]);
        o1.y = fmaf(s_std[i2 + 1], n1.y, s_mean[i2 + 1]);
        o1.z = fmaf(s_std[i3 + 0], n1.z, s_mean[i3 + 0]);
        o1.w = fmaf(s_std[i3 + 1], n1.w, s_mean[i3 + 1]);
    }

    float4* op = reinterpret_cast<float4*>(out + v * CCH);
    op[0] = o0;
    op[1] = o1;
}

extern "C" void kernel_launch(void* const* d_in, const int* in_sizes, int n_in,
                              void* d_out, int out_size)
{
    const int*   label = (const int*)  d_in[0];  // [2,160,160,160,1]
    const float* means = (const float*)d_in[1];  // [2,25,2]
    const float* stds  = (const float*)d_in[2];  // [2,25,2]
    const float* noise = (const float*)d_in[3];  // [2,160,160,160,2]
    float*       out   = (float*)d_out;

    const int total_vox = 2 * VOX;               // 8,192,000
    const int blocks = total_vox / VPB;          // 8000
    gmm_sample_kernel<<<blocks, 256>>>(label, means, stds, noise, out);
}